// round 12
// baseline (speedup 1.0000x reference)
#include <cuda_runtime.h>
#include <cuda_fp16.h>
#include <math.h>
#include <stdint.h>

// ---------------------------------------------------------------------------
// Problem constants
// ---------------------------------------------------------------------------
#define B_ 4
#define T_ 2048
#define H_ 1024
#define DFF_ 4096
#define M_ (B_ * T_)      // 8192 tokens
#define HALF_ (H_ / 2)    // 512
#define ACT_TAU 0.99f
#define TARGET_DEPTH 2.5f
#define BUDGET_WEIGHT 0.01f
#define RW1_ROWS 1025

// ---------------------------------------------------------------------------
// Device scratch (no allocations allowed)
// ---------------------------------------------------------------------------
__device__ __align__(16) __half g_W1h[(size_t)H_ * DFF_];
__device__ __align__(16) __half g_W2h[(size_t)DFF_ * H_];
__device__ __align__(16) __half g_R1h[(size_t)3 * RW1_ROWS * HALF_];
__device__ __align__(16) __half g_xh[(size_t)M_ * H_];
__device__ __align__(16) __half g_xl[(size_t)M_ * H_];
__device__ __align__(16) __half g_hh[(size_t)M_ * DFF_];
__device__ __align__(16) __half g_hl[(size_t)M_ * DFF_];
__device__ float g_x[(size_t)M_ * H_];
__device__ float g_rh[(size_t)M_ * HALF_];
__device__ float g_w[M_];
__device__ float g_cum[M_];
__device__ float g_still[M_];
__device__ float g_wsum[M_];

// ---------------------------------------------------------------------------
// Helpers
// ---------------------------------------------------------------------------
__device__ __forceinline__ uint32_t smem_u32(const void* p) {
    uint32_t a;
    asm("{ .reg .u64 t; cvta.to.shared.u64 t, %1; cvt.u32.u64 %0, t; }"
        : "=r"(a) : "l"(p));
    return a;
}

__device__ __forceinline__ float gelu_exact(float v) {
    return 0.5f * v * (1.0f + erff(v * 0.70710678118654752440f));
}

__device__ __forceinline__ void cpa16(uint32_t dst, const void* src) {
    asm volatile("cp.async.cg.shared.global [%0], [%1], 16;" :: "r"(dst), "l"(src));
}
__device__ __forceinline__ void cpa_commit() {
    asm volatile("cp.async.commit_group;" ::: "memory");
}
template <int N>
__device__ __forceinline__ void cpa_wait() {
    asm volatile("cp.async.wait_group %0;" :: "n"(N) : "memory");
}

__device__ __forceinline__ void ldsm_x4(uint32_t* r, uint32_t addr) {
    asm volatile("ldmatrix.sync.aligned.m8n8.x4.shared.b16 {%0,%1,%2,%3}, [%4];"
                 : "=r"(r[0]), "=r"(r[1]), "=r"(r[2]), "=r"(r[3]) : "r"(addr));
}
__device__ __forceinline__ void ldsm_x4t(uint32_t* r, uint32_t addr) {
    asm volatile("ldmatrix.sync.aligned.m8n8.x4.trans.shared.b16 {%0,%1,%2,%3}, [%4];"
                 : "=r"(r[0]), "=r"(r[1]), "=r"(r[2]), "=r"(r[3]) : "r"(addr));
}

// mma m16n8k16 fp16 -> fp32 accum
__device__ __forceinline__ void mma_f16(float* c, const uint32_t* a,
                                        uint32_t b0, uint32_t b1) {
    asm volatile(
        "mma.sync.aligned.m16n8k16.row.col.f32.f16.f16.f32 "
        "{%0,%1,%2,%3}, {%4,%5,%6,%7}, {%8,%9}, {%0,%1,%2,%3};"
        : "+f"(c[0]), "+f"(c[1]), "+f"(c[2]), "+f"(c[3])
        : "r"(a[0]), "r"(a[1]), "r"(a[2]), "r"(a[3]), "r"(b0), "r"(b1));
}

// ---------------------------------------------------------------------------
// Splits
// ---------------------------------------------------------------------------
__global__ void split_kernel(const float* __restrict__ src, __half* __restrict__ hi,
                             __half* __restrict__ lo, int n4)
{
    int i = blockIdx.x * 256 + threadIdx.x;
    if (i >= n4) return;
    float4 v = ((const float4*)src)[i];
    __half hx = __float2half_rn(v.x), hy = __float2half_rn(v.y);
    __half hz = __float2half_rn(v.z), hw = __float2half_rn(v.w);
    ((__half2*)hi)[i * 2 + 0] = __halves2half2(hx, hy);
    ((__half2*)hi)[i * 2 + 1] = __halves2half2(hz, hw);
    __half lx = __float2half_rn(v.x - __half2float(hx));
    __half ly = __float2half_rn(v.y - __half2float(hy));
    __half lz = __float2half_rn(v.z - __half2float(hz));
    __half lw = __float2half_rn(v.w - __half2float(hw));
    ((__half2*)lo)[i * 2 + 0] = __halves2half2(lx, ly);
    ((__half2*)lo)[i * 2 + 1] = __halves2half2(lz, lw);
}

__global__ void split_hi_kernel(const float* __restrict__ src,
                                __half* __restrict__ hi, int n4)
{
    int i = blockIdx.x * 256 + threadIdx.x;
    if (i >= n4) return;
    float4 v = ((const float4*)src)[i];
    ((__half2*)hi)[i * 2 + 0] = __halves2half2(__float2half_rn(v.x), __float2half_rn(v.y));
    ((__half2*)hi)[i * 2 + 1] = __halves2half2(__float2half_rn(v.z), __float2half_rn(v.w));
}

// ---------------------------------------------------------------------------
// Shared tile config
// ---------------------------------------------------------------------------
#define TBM 128
#define TBN 128
#define TBK 32
#define AST 80       // A smem row stride bytes (32 fp16 = 64B + 16 pad)
#define BST 272      // B smem row stride bytes (128 fp16 = 256B + 16 pad)
#define A_BYTES (128 * AST)                 // 10240
#define B_BYTES (32 * BST)                  // 8704
#define ST_AH 0
#define ST_AL A_BYTES
#define ST_BH (2 * A_BYTES)
#define STAGE_BYTES (2 * A_BYTES + B_BYTES) // 29184
#define SMEM_BYTES (2 * STAGE_BYTES)        // 58368

// Mainloop macro body shared by both kernels.
// Computes acc[2][8][4] = (A_hi + A_lo) * W_hi over K, 2-stage cp.async.
// Per k16-step: preload ALL B fragments, then full hi pass, then full lo pass
// (per-accumulator order hi-then-lo unchanged -> bit-identical numerics; the
// same-accumulator reuse distance grows to 16 MMAs, hiding HMMA RAW latency).
#define GEMM_MAINLOOP(Ah_, Al_, Wh_, ldw_, K_)                                   \
    const int NC = (K_) / TBK;                                                   \
    auto load_chunk = [&](int c) {                                               \
        const uint32_t st = sm + (uint32_t)((c & 1) * STAGE_BYTES);              \
        const int k0 = c * TBK;                                                  \
        _Pragma("unroll")                                                        \
        for (int s = 0; s < 2; s++) {                                            \
            int gidx = tid + 256 * s;                                            \
            int r = gidx >> 2, o = gidx & 3;                                     \
            size_t go = (size_t)(row_base + r) * (K_) + k0 + o * 8;              \
            uint32_t so = (uint32_t)(r * AST + o * 16);                          \
            cpa16(st + ST_AH + so, (Ah_) + go);                                  \
            cpa16(st + ST_AL + so, (Al_) + go);                                  \
        }                                                                        \
        _Pragma("unroll")                                                        \
        for (int s = 0; s < 2; s++) {                                            \
            int gidx = tid + 256 * s;                                            \
            int r = gidx >> 4, o = gidx & 15;                                    \
            size_t go = (size_t)(k0 + r) * (ldw_) + col_base + o * 8;            \
            uint32_t so = (uint32_t)(r * BST + o * 16);                          \
            cpa16(st + ST_BH + so, (Wh_) + go);                                  \
        }                                                                        \
        cpa_commit();                                                            \
    };                                                                           \
    load_chunk(0);                                                               \
    for (int c = 0; c < NC; c++) {                                               \
        if (c + 1 < NC) { load_chunk(c + 1); cpa_wait<1>(); }                    \
        else            { cpa_wait<0>(); }                                       \
        __syncthreads();                                                         \
        const uint32_t st = sm + (uint32_t)((c & 1) * STAGE_BYTES);              \
        _Pragma("unroll")                                                        \
        for (int ks = 0; ks < 2; ks++) {                                         \
            uint32_t ah[2][4], al[2][4], bh[4][4];                               \
            _Pragma("unroll")                                                    \
            for (int mi = 0; mi < 2; mi++) {                                     \
                uint32_t ao = a_lane + (uint32_t)(mi * 16 * AST + ks * 32);      \
                ldsm_x4(ah[mi], st + ST_AH + ao);                                \
                ldsm_x4(al[mi], st + ST_AL + ao);                                \
            }                                                                    \
            _Pragma("unroll")                                                    \
            for (int ni = 0; ni < 4; ni++)                                       \
                ldsm_x4t(bh[ni], st + ST_BH + b_lane +                           \
                                 (uint32_t)(ks * 16 * BST + ni * 32));           \
            _Pragma("unroll")                                                    \
            for (int ni = 0; ni < 4; ni++)                                       \
                _Pragma("unroll")                                                \
                for (int mi = 0; mi < 2; mi++) {                                 \
                    mma_f16(acc[mi][ni * 2 + 0], ah[mi], bh[ni][0], bh[ni][1]);  \
                    mma_f16(acc[mi][ni * 2 + 1], ah[mi], bh[ni][2], bh[ni][3]);  \
                }                                                                \
            _Pragma("unroll")                                                    \
            for (int ni = 0; ni < 4; ni++)                                       \
                _Pragma("unroll")                                                \
                for (int mi = 0; mi < 2; mi++) {                                 \
                    mma_f16(acc[mi][ni * 2 + 0], al[mi], bh[ni][0], bh[ni][1]);  \
                    mma_f16(acc[mi][ni * 2 + 1], al[mi], bh[ni][2], bh[ni][3]);  \
                }                                                                \
        }                                                                        \
        __syncthreads();                                                         \
    }

// ---------------------------------------------------------------------------
// Fused body-GEMM1 + router-GEMM kernel.
// grid.x = 32 body N-tiles (+4 router N-tiles when Rw present).
//   bx < 32 : h-tile  = gelu(x*W1 + bb1)      -> hh/hl (fp16 split, ld 4096)
//   bx >= 32: rh-tile = gelu(x*Rw1_i + Rb1_i) -> rh (fp32, ld 512)
// ---------------------------------------------------------------------------
__global__ __launch_bounds__(256, 2)
void g1_router(const __half* __restrict__ Ah, const __half* __restrict__ Al,
               const __half* __restrict__ W1, const float* __restrict__ b1,
               __half* __restrict__ Chh, __half* __restrict__ Chl,
               const __half* __restrict__ Wr, const float* __restrict__ br,
               float* __restrict__ Crh)
{
    extern __shared__ char smp[];
    const uint32_t sm = smem_u32(smp);

    const int tid = threadIdx.x;
    const int lane = tid & 31;
    const int warp = tid >> 5;
    const int warp_m = warp & 3;
    const int warp_n = warp >> 2;
    const int row_base = blockIdx.y * TBM;

    const bool is_r = (blockIdx.x >= 32);
    const int col_base = (is_r ? (blockIdx.x - 32) : blockIdx.x) * TBN;
    const __half* Wh = is_r ? Wr : W1;
    const float* bias = is_r ? br : b1;
    const int ldw = is_r ? HALF_ : DFF_;

    float acc[2][8][4];
#pragma unroll
    for (int i = 0; i < 2; i++)
#pragma unroll
        for (int j = 0; j < 8; j++)
#pragma unroll
            for (int k = 0; k < 4; k++) acc[i][j][k] = 0.0f;

    const uint32_t a_lane = (uint32_t)((warp_m * 32 + (lane & 15)) * AST +
                                       (lane >> 4) * 16);
    const uint32_t b_lane = (uint32_t)((((lane >> 3) & 1) * 8 + (lane & 7)) * BST +
                                       (warp_n * 64 + (lane >> 4) * 8) * 2);

    GEMM_MAINLOOP(Ah, Al, Wh, ldw, H_)

    // epilogue: gelu always; router writes fp32, body writes fp16 hi/lo
    const int g = lane >> 2;
    const int tg = lane & 3;
    float bv0[8], bv1[8];
#pragma unroll
    for (int nj = 0; nj < 8; nj++) {
        const int gcol = col_base + warp_n * 64 + nj * 8 + tg * 2;
        bv0[nj] = bias[gcol];
        bv1[nj] = bias[gcol + 1];
    }

#pragma unroll
    for (int mi = 0; mi < 2; mi++) {
        const int r0 = row_base + warp_m * 32 + mi * 16 + g;
        const int r1 = r0 + 8;
#pragma unroll
        for (int nj = 0; nj < 8; nj++) {
            const int gcol = col_base + warp_n * 64 + nj * 8 + tg * 2;
            float v00 = gelu_exact(acc[mi][nj][0] + bv0[nj]);
            float v01 = gelu_exact(acc[mi][nj][1] + bv1[nj]);
            float v10 = gelu_exact(acc[mi][nj][2] + bv0[nj]);
            float v11 = gelu_exact(acc[mi][nj][3] + bv1[nj]);
            if (is_r) {
                *(float2*)&Crh[(size_t)r0 * HALF_ + gcol] = make_float2(v00, v01);
                *(float2*)&Crh[(size_t)r1 * HALF_ + gcol] = make_float2(v10, v11);
            } else {
                __half h00 = __float2half_rn(v00), h01 = __float2half_rn(v01);
                __half h10 = __float2half_rn(v10), h11 = __float2half_rn(v11);
                *(__half2*)&Chh[(size_t)r0 * DFF_ + gcol] = __halves2half2(h00, h01);
                *(__half2*)&Chh[(size_t)r1 * DFF_ + gcol] = __halves2half2(h10, h11);
                __half l00 = __float2half_rn(v00 - __half2float(h00));
                __half l01 = __float2half_rn(v01 - __half2float(h01));
                __half l10 = __float2half_rn(v10 - __half2float(h10));
                __half l11 = __float2half_rn(v11 - __half2float(h11));
                *(__half2*)&Chl[(size_t)r0 * DFF_ + gcol] = __halves2half2(l00, l01);
                *(__half2*)&Chl[(size_t)r1 * DFF_ + gcol] = __halves2half2(l10, l11);
            }
        }
    }
}

// ---------------------------------------------------------------------------
// Generic GEMM (used for body GEMM2).
// EPI: 0=bias, 2=bias+ACT mix.  WF: write fp32.  WH: write fp16 hi/lo.
// ---------------------------------------------------------------------------
template <int EPI, int WF, int WH>
__global__ __launch_bounds__(256, 2)
void tgemm(const __half* __restrict__ Ah, const __half* __restrict__ Al,
           const __half* __restrict__ Wh,
           const float* __restrict__ bias, float* __restrict__ Cf,
           __half* __restrict__ Chh, __half* __restrict__ Chl,
           int M, int N, int K,
           const float* __restrict__ wmix, const float* __restrict__ xold)
{
    extern __shared__ char smp[];
    const uint32_t sm = smem_u32(smp);

    const int tid = threadIdx.x;
    const int lane = tid & 31;
    const int warp = tid >> 5;
    const int warp_m = warp & 3;
    const int warp_n = warp >> 2;
    const int row_base = blockIdx.y * TBM;
    const int col_base = blockIdx.x * TBN;

    float acc[2][8][4];
#pragma unroll
    for (int i = 0; i < 2; i++)
#pragma unroll
        for (int j = 0; j < 8; j++)
#pragma unroll
            for (int k = 0; k < 4; k++) acc[i][j][k] = 0.0f;

    const uint32_t a_lane = (uint32_t)((warp_m * 32 + (lane & 15)) * AST +
                                       (lane >> 4) * 16);
    const uint32_t b_lane = (uint32_t)((((lane >> 3) & 1) * 8 + (lane & 7)) * BST +
                                       (warp_n * 64 + (lane >> 4) * 8) * 2);

    GEMM_MAINLOOP(Ah, Al, Wh, N, K)

    const int g = lane >> 2;
    const int tg = lane & 3;
    float bv0[8], bv1[8];
#pragma unroll
    for (int nj = 0; nj < 8; nj++) {
        const int gcol = col_base + warp_n * 64 + nj * 8 + tg * 2;
        bv0[nj] = bias[gcol];
        bv1[nj] = bias[gcol + 1];
    }

#pragma unroll
    for (int mi = 0; mi < 2; mi++) {
        const int r0 = row_base + warp_m * 32 + mi * 16 + g;
        const int r1 = r0 + 8;
        float w0 = 0.0f, w1 = 0.0f;
        if (EPI == 2) { w0 = wmix[r0]; w1 = wmix[r1]; }
#pragma unroll
        for (int nj = 0; nj < 8; nj++) {
            const int gcol = col_base + warp_n * 64 + nj * 8 + tg * 2;
            float v00 = acc[mi][nj][0] + bv0[nj], v01 = acc[mi][nj][1] + bv1[nj];
            float v10 = acc[mi][nj][2] + bv0[nj], v11 = acc[mi][nj][3] + bv1[nj];
            if (EPI == 2) {
                float2 xo0 = *(const float2*)&xold[(size_t)r0 * N + gcol];
                float2 xo1 = *(const float2*)&xold[(size_t)r1 * N + gcol];
                v00 = w0 * v00 + (1.0f - w0) * xo0.x;
                v01 = w0 * v01 + (1.0f - w0) * xo0.y;
                v10 = w1 * v10 + (1.0f - w1) * xo1.x;
                v11 = w1 * v11 + (1.0f - w1) * xo1.y;
            }
            if (WF) {
                *(float2*)&Cf[(size_t)r0 * N + gcol] = make_float2(v00, v01);
                *(float2*)&Cf[(size_t)r1 * N + gcol] = make_float2(v10, v11);
            }
            if (WH) {
                __half h00 = __float2half_rn(v00), h01 = __float2half_rn(v01);
                __half h10 = __float2half_rn(v10), h11 = __float2half_rn(v11);
                *(__half2*)&Chh[(size_t)r0 * N + gcol] = __halves2half2(h00, h01);
                *(__half2*)&Chh[(size_t)r1 * N + gcol] = __halves2half2(h10, h11);
                __half l00 = __float2half_rn(v00 - __half2float(h00));
                __half l01 = __float2half_rn(v01 - __half2float(h01));
                __half l10 = __float2half_rn(v10 - __half2float(h10));
                __half l11 = __float2half_rn(v11 - __half2float(h11));
                *(__half2*)&Chl[(size_t)r0 * N + gcol] = __halves2half2(l00, l01);
                *(__half2*)&Chl[(size_t)r1 * N + gcol] = __halves2half2(l10, l11);
            }
        }
    }
}

// ---------------------------------------------------------------------------
// Router head GEMV + ACT state update (one warp per token)
// ---------------------------------------------------------------------------
__global__ void router_act_kernel(const float* __restrict__ rh,
                                  const float* __restrict__ Rw2i,
                                  const float* __restrict__ Rb2i)
{
    const int warp = threadIdx.x >> 5;
    const int lane = threadIdx.x & 31;
    const int t = blockIdx.x * 8 + warp;
    if (t >= M_) return;

    const float* r = rh + (size_t)t * HALF_;
    float s = 0.0f;
#pragma unroll
    for (int k = lane; k < HALF_; k += 32) s += r[k] * Rw2i[k];
#pragma unroll
    for (int o = 16; o > 0; o >>= 1) s += __shfl_xor_sync(0xffffffffu, s, o);

    if (lane == 0) {
        const float logit = s + Rb2i[0];
        const float p = 1.0f / (1.0f + expf(-logit));
        const float cum = g_cum[t];
        const float still = g_still[t];
        const float rem = fmaxf(1.0f - cum, 0.0f);
        const bool halt = (cum + p >= ACT_TAU);
        const float w = (halt ? rem : p) * still;
        g_w[t] = w;
        g_cum[t] = cum + w;
        g_wsum[t] += w;
        g_still[t] = halt ? 0.0f : still;
    }
}

__global__ void init_state_kernel()
{
    const int t = blockIdx.x * 256 + threadIdx.x;
    if (t < M_) {
        g_cum[t] = 0.0f;
        g_still[t] = 1.0f;
        g_wsum[t] = 1.0f;
    }
}

__global__ void budget_kernel(float* __restrict__ out)
{
    __shared__ float sh[256];
    float s = 0.0f;
    for (int t = threadIdx.x; t < M_; t += 256) s += g_wsum[t];
    sh[threadIdx.x] = s;
    __syncthreads();
#pragma unroll
    for (int o = 128; o > 0; o >>= 1) {
        if (threadIdx.x < o) sh[threadIdx.x] += sh[threadIdx.x + o];
        __syncthreads();
    }
    if (threadIdx.x == 0) {
        const float avg = sh[0] / (float)M_;
        const float d = avg - TARGET_DEPTH;
        const float rl = d > 0.0f ? d : 0.0f;
        out[0] = BUDGET_WEIGHT * rl * rl;
    }
}

// ---------------------------------------------------------------------------
// Launch
// ---------------------------------------------------------------------------
extern "C" void kernel_launch(void* const* d_in, const int* in_sizes, int n_in,
                              void* d_out, int out_size)
{
    const float* x_in = (const float*)d_in[0];
    const float* Wb1  = (const float*)d_in[1];
    const float* bb1  = (const float*)d_in[2];
    const float* Wb2  = (const float*)d_in[3];
    const float* bb2  = (const float*)d_in[4];
    const float* Rw1  = (const float*)d_in[5];  // (3, 1025, 512)
    const float* Rb1  = (const float*)d_in[6];  // (3, 512)
    const float* Rw2  = (const float*)d_in[7];  // (3, 512, 1)
    const float* Rb2  = (const float*)d_in[8];  // (3, 1)
    float* out = (float*)d_out;

    cudaFuncSetAttribute(g1_router,   cudaFuncAttributeMaxDynamicSharedMemorySize, SMEM_BYTES);
    cudaFuncSetAttribute(tgemm<0,1,1>, cudaFuncAttributeMaxDynamicSharedMemorySize, SMEM_BYTES);
    cudaFuncSetAttribute(tgemm<2,1,1>, cudaFuncAttributeMaxDynamicSharedMemorySize, SMEM_BYTES);
    cudaFuncSetAttribute(tgemm<2,1,0>, cudaFuncAttributeMaxDynamicSharedMemorySize, SMEM_BYTES);

    __half *W1h, *W2h, *R1h, *xh, *xl, *hh, *hl;
    float *gx, *grh, *gw;
    cudaGetSymbolAddress((void**)&W1h, g_W1h);
    cudaGetSymbolAddress((void**)&W2h, g_W2h);
    cudaGetSymbolAddress((void**)&R1h, g_R1h);
    cudaGetSymbolAddress((void**)&xh,  g_xh);
    cudaGetSymbolAddress((void**)&xl,  g_xl);
    cudaGetSymbolAddress((void**)&hh,  g_hh);
    cudaGetSymbolAddress((void**)&hl,  g_hl);
    cudaGetSymbolAddress((void**)&gx,  g_x);
    cudaGetSymbolAddress((void**)&grh, g_rh);
    cudaGetSymbolAddress((void**)&gw,  g_w);

    init_state_kernel<<<M_ / 256, 256>>>();

    // pre-split: weights hi-only (B operand), input activations hi+lo (A operand)
    {
        int n4;
        n4 = H_ * DFF_ / 4;
        split_hi_kernel<<<(n4 + 255) / 256, 256>>>(Wb1, W1h, n4);
        split_hi_kernel<<<(n4 + 255) / 256, 256>>>(Wb2, W2h, n4);
        n4 = 3 * RW1_ROWS * HALF_ / 4;
        split_hi_kernel<<<(n4 + 255) / 256, 256>>>(Rw1, R1h, n4);
        n4 = M_ * H_ / 4;
        split_kernel<<<(n4 + 255) / 256, 256>>>(x_in, xh, xl, n4);
    }

    dim3 blk(256);
    dim3 gr1(32, M_ / TBM);            // body GEMM1 alone (first pass)
    dim3 gr1r(36, M_ / TBM);           // body GEMM1 + fused router tiles
    dim3 gr2(H_ / TBN, M_ / TBM);      // body GEMM2: 8 x 64

    // Mandatory first body pass: h = gelu(x W1 + b1); x = h W2 + b2
    g1_router<<<gr1, blk, SMEM_BYTES>>>(xh, xl, W1h, bb1, hh, hl,
                                        R1h, Rb1, grh);
    tgemm<0,1,1><<<gr2, blk, SMEM_BYTES>>>(hh, hl, W2h, bb2, gx, xh, xl,
                                           M_, H_, DFF_, nullptr, nullptr);

    for (int i = 0; i < 3; i++) {
        // Fused: h = gelu(x W1 + b1)  AND  rh = gelu(x Rw1_i + Rb1_i)
        const __half* R1hi = R1h + (size_t)i * RW1_ROWS * HALF_;
        g1_router<<<gr1r, blk, SMEM_BYTES>>>(xh, xl, W1h, bb1, hh, hl,
                                             R1hi, Rb1 + i * HALF_, grh);
        router_act_kernel<<<M_ / 8, 256>>>(grh, Rw2 + (size_t)i * HALF_, Rb2 + i);

        // Body GEMM2 + fused ACT soft mix
        if (i < 2) {
            tgemm<2,1,1><<<gr2, blk, SMEM_BYTES>>>(hh, hl, W2h, bb2, gx, xh, xl,
                                                   M_, H_, DFF_, gw, gx);
        } else {
            tgemm<2,1,0><<<gr2, blk, SMEM_BYTES>>>(hh, hl, W2h, bb2, out,
                                                   nullptr, nullptr,
                                                   M_, H_, DFF_, gw, gx);
        }
    }

    if (out_size > (int)((size_t)M_ * H_))
        budget_kernel<<<1, 256>>>(out + (size_t)M_ * H_);
}

// round 13
// speedup vs baseline: 1.7067x; 1.7067x over previous
#include <cuda_runtime.h>
#include <cuda_fp16.h>
#include <math.h>
#include <stdint.h>

// ---------------------------------------------------------------------------
// Problem constants
// ---------------------------------------------------------------------------
#define B_ 4
#define T_ 2048
#define H_ 1024
#define DFF_ 4096
#define M_ (B_ * T_)      // 8192 tokens
#define HALF_ (H_ / 2)    // 512
#define ACT_TAU 0.99f
#define TARGET_DEPTH 2.5f
#define BUDGET_WEIGHT 0.01f
#define RW1_ROWS 1025

// ---------------------------------------------------------------------------
// Device scratch (no allocations allowed)
// ---------------------------------------------------------------------------
__device__ __align__(16) __half g_W1h[(size_t)H_ * DFF_];
__device__ __align__(16) __half g_W2h[(size_t)DFF_ * H_];
__device__ __align__(16) __half g_R1h[(size_t)3 * RW1_ROWS * HALF_];
__device__ __align__(16) __half g_xh[(size_t)M_ * H_];
__device__ __align__(16) __half g_hh[(size_t)M_ * DFF_];
__device__ float g_x[(size_t)M_ * H_];
__device__ float g_rh[(size_t)M_ * HALF_];
__device__ float g_w[M_];
__device__ float g_cum[M_];
__device__ float g_still[M_];
__device__ float g_wsum[M_];

// ---------------------------------------------------------------------------
// Helpers
// ---------------------------------------------------------------------------
__device__ __forceinline__ uint32_t smem_u32(const void* p) {
    uint32_t a;
    asm("{ .reg .u64 t; cvta.to.shared.u64 t, %1; cvt.u32.u64 %0, t; }"
        : "=r"(a) : "l"(p));
    return a;
}

__device__ __forceinline__ float gelu_exact(float v) {
    return 0.5f * v * (1.0f + erff(v * 0.70710678118654752440f));
}

__device__ __forceinline__ void cpa16(uint32_t dst, const void* src) {
    asm volatile("cp.async.cg.shared.global [%0], [%1], 16;" :: "r"(dst), "l"(src));
}
__device__ __forceinline__ void cpa_commit() {
    asm volatile("cp.async.commit_group;" ::: "memory");
}
template <int N>
__device__ __forceinline__ void cpa_wait() {
    asm volatile("cp.async.wait_group %0;" :: "n"(N) : "memory");
}

__device__ __forceinline__ void ldsm_x4(uint32_t* r, uint32_t addr) {
    asm volatile("ldmatrix.sync.aligned.m8n8.x4.shared.b16 {%0,%1,%2,%3}, [%4];"
                 : "=r"(r[0]), "=r"(r[1]), "=r"(r[2]), "=r"(r[3]) : "r"(addr));
}
__device__ __forceinline__ void ldsm_x4t(uint32_t* r, uint32_t addr) {
    asm volatile("ldmatrix.sync.aligned.m8n8.x4.trans.shared.b16 {%0,%1,%2,%3}, [%4];"
                 : "=r"(r[0]), "=r"(r[1]), "=r"(r[2]), "=r"(r[3]) : "r"(addr));
}

// mma m16n8k16 fp16 -> fp32 accum
__device__ __forceinline__ void mma_f16(float* c, const uint32_t* a,
                                        uint32_t b0, uint32_t b1) {
    asm volatile(
        "mma.sync.aligned.m16n8k16.row.col.f32.f16.f16.f32 "
        "{%0,%1,%2,%3}, {%4,%5,%6,%7}, {%8,%9}, {%0,%1,%2,%3};"
        : "+f"(c[0]), "+f"(c[1]), "+f"(c[2]), "+f"(c[3])
        : "r"(a[0]), "r"(a[1]), "r"(a[2]), "r"(a[3]), "r"(b0), "r"(b1));
}

// ---------------------------------------------------------------------------
// fp32 -> fp16 convert
// ---------------------------------------------------------------------------
__global__ void split_hi_kernel(const float* __restrict__ src,
                                __half* __restrict__ hi, int n4)
{
    int i = blockIdx.x * 256 + threadIdx.x;
    if (i >= n4) return;
    float4 v = ((const float4*)src)[i];
    ((__half2*)hi)[i * 2 + 0] = __halves2half2(__float2half_rn(v.x), __float2half_rn(v.y));
    ((__half2*)hi)[i * 2 + 1] = __halves2half2(__float2half_rn(v.z), __float2half_rn(v.w));
}

// ---------------------------------------------------------------------------
// Shared tile config (pure fp16 single-pass)
// ---------------------------------------------------------------------------
#define TBM 128
#define TBN 128
#define TBK 32
#define AST 80       // A smem row stride bytes (32 fp16 = 64B + 16 pad)
#define BST 272      // B smem row stride bytes (128 fp16 = 256B + 16 pad)
#define A_BYTES (128 * AST)                 // 10240
#define B_BYTES (32 * BST)                  // 8704
#define ST_AH 0
#define ST_BH A_BYTES
#define STAGE_BYTES (A_BYTES + B_BYTES)     // 18944
#define SMEM_BYTES (2 * STAGE_BYTES)        // 37888

// Mainloop: acc[2][8][4] = A_h[M,K] * W_h[K,N], 2-stage cp.async pipeline.
#define GEMM_MAINLOOP(Ah_, Wh_, ldw_, K_)                                        \
    const int NC = (K_) / TBK;                                                   \
    auto load_chunk = [&](int c) {                                               \
        const uint32_t st = sm + (uint32_t)((c & 1) * STAGE_BYTES);              \
        const int k0 = c * TBK;                                                  \
        _Pragma("unroll")                                                        \
        for (int s = 0; s < 2; s++) {                                            \
            int gidx = tid + 256 * s;                                            \
            int r = gidx >> 2, o = gidx & 3;                                     \
            size_t go = (size_t)(row_base + r) * (K_) + k0 + o * 8;              \
            cpa16(st + ST_AH + (uint32_t)(r * AST + o * 16), (Ah_) + go);        \
        }                                                                        \
        _Pragma("unroll")                                                        \
        for (int s = 0; s < 2; s++) {                                            \
            int gidx = tid + 256 * s;                                            \
            int r = gidx >> 4, o = gidx & 15;                                    \
            size_t go = (size_t)(k0 + r) * (ldw_) + col_base + o * 8;            \
            cpa16(st + ST_BH + (uint32_t)(r * BST + o * 16), (Wh_) + go);        \
        }                                                                        \
        cpa_commit();                                                            \
    };                                                                           \
    load_chunk(0);                                                               \
    for (int c = 0; c < NC; c++) {                                               \
        if (c + 1 < NC) { load_chunk(c + 1); cpa_wait<1>(); }                    \
        else            { cpa_wait<0>(); }                                       \
        __syncthreads();                                                         \
        const uint32_t st = sm + (uint32_t)((c & 1) * STAGE_BYTES);              \
        _Pragma("unroll")                                                        \
        for (int ks = 0; ks < 2; ks++) {                                         \
            uint32_t ah[2][4], bh[4][4];                                         \
            _Pragma("unroll")                                                    \
            for (int mi = 0; mi < 2; mi++)                                       \
                ldsm_x4(ah[mi], st + ST_AH + a_lane +                            \
                                (uint32_t)(mi * 16 * AST + ks * 32));            \
            _Pragma("unroll")                                                    \
            for (int ni = 0; ni < 4; ni++)                                       \
                ldsm_x4t(bh[ni], st + ST_BH + b_lane +                           \
                                 (uint32_t)(ks * 16 * BST + ni * 32));           \
            _Pragma("unroll")                                                    \
            for (int ni = 0; ni < 4; ni++)                                       \
                _Pragma("unroll")                                                \
                for (int mi = 0; mi < 2; mi++) {                                 \
                    mma_f16(acc[mi][ni * 2 + 0], ah[mi], bh[ni][0], bh[ni][1]);  \
                    mma_f16(acc[mi][ni * 2 + 1], ah[mi], bh[ni][2], bh[ni][3]);  \
                }                                                                \
        }                                                                        \
        __syncthreads();                                                         \
    }

// ---------------------------------------------------------------------------
// Fused body-GEMM1 + router-GEMM kernel.
//   bx < 32 : h-tile  = gelu(x*W1 + bb1)      -> hh (fp16, ld 4096)
//   bx >= 32: rh-tile = gelu(x*Rw1_i + Rb1_i) -> rh (fp32, ld 512)
// ---------------------------------------------------------------------------
__global__ __launch_bounds__(256, 2)
void g1_router(const __half* __restrict__ Ah,
               const __half* __restrict__ W1, const float* __restrict__ b1,
               __half* __restrict__ Chh,
               const __half* __restrict__ Wr, const float* __restrict__ br,
               float* __restrict__ Crh)
{
    extern __shared__ char smp[];
    const uint32_t sm = smem_u32(smp);

    const int tid = threadIdx.x;
    const int lane = tid & 31;
    const int warp = tid >> 5;
    const int warp_m = warp & 3;
    const int warp_n = warp >> 2;
    const int row_base = blockIdx.y * TBM;

    const bool is_r = (blockIdx.x >= 32);
    const int col_base = (is_r ? (blockIdx.x - 32) : blockIdx.x) * TBN;
    const __half* Wh = is_r ? Wr : W1;
    const float* bias = is_r ? br : b1;
    const int ldw = is_r ? HALF_ : DFF_;

    float acc[2][8][4];
#pragma unroll
    for (int i = 0; i < 2; i++)
#pragma unroll
        for (int j = 0; j < 8; j++)
#pragma unroll
            for (int k = 0; k < 4; k++) acc[i][j][k] = 0.0f;

    const uint32_t a_lane = (uint32_t)((warp_m * 32 + (lane & 15)) * AST +
                                       (lane >> 4) * 16);
    const uint32_t b_lane = (uint32_t)((((lane >> 3) & 1) * 8 + (lane & 7)) * BST +
                                       (warp_n * 64 + (lane >> 4) * 8) * 2);

    GEMM_MAINLOOP(Ah, Wh, ldw, H_)

    const int g = lane >> 2;
    const int tg = lane & 3;
    float bv0[8], bv1[8];
#pragma unroll
    for (int nj = 0; nj < 8; nj++) {
        const int gcol = col_base + warp_n * 64 + nj * 8 + tg * 2;
        bv0[nj] = bias[gcol];
        bv1[nj] = bias[gcol + 1];
    }

#pragma unroll
    for (int mi = 0; mi < 2; mi++) {
        const int r0 = row_base + warp_m * 32 + mi * 16 + g;
        const int r1 = r0 + 8;
#pragma unroll
        for (int nj = 0; nj < 8; nj++) {
            const int gcol = col_base + warp_n * 64 + nj * 8 + tg * 2;
            float v00 = gelu_exact(acc[mi][nj][0] + bv0[nj]);
            float v01 = gelu_exact(acc[mi][nj][1] + bv1[nj]);
            float v10 = gelu_exact(acc[mi][nj][2] + bv0[nj]);
            float v11 = gelu_exact(acc[mi][nj][3] + bv1[nj]);
            if (is_r) {
                *(float2*)&Crh[(size_t)r0 * HALF_ + gcol] = make_float2(v00, v01);
                *(float2*)&Crh[(size_t)r1 * HALF_ + gcol] = make_float2(v10, v11);
            } else {
                *(__half2*)&Chh[(size_t)r0 * DFF_ + gcol] =
                    __halves2half2(__float2half_rn(v00), __float2half_rn(v01));
                *(__half2*)&Chh[(size_t)r1 * DFF_ + gcol] =
                    __halves2half2(__float2half_rn(v10), __float2half_rn(v11));
            }
        }
    }
}

// ---------------------------------------------------------------------------
// Generic GEMM (used for body GEMM2).
// EPI: 0=bias, 2=bias+ACT mix.  WF: write fp32 Cf.  WH: write fp16 Chh.
// ---------------------------------------------------------------------------
template <int EPI, int WF, int WH>
__global__ __launch_bounds__(256, 2)
void tgemm(const __half* __restrict__ Ah, const __half* __restrict__ Wh,
           const float* __restrict__ bias, float* __restrict__ Cf,
           __half* __restrict__ Chh,
           int M, int N, int K,
           const float* __restrict__ wmix, const float* __restrict__ xold)
{
    extern __shared__ char smp[];
    const uint32_t sm = smem_u32(smp);

    const int tid = threadIdx.x;
    const int lane = tid & 31;
    const int warp = tid >> 5;
    const int warp_m = warp & 3;
    const int warp_n = warp >> 2;
    const int row_base = blockIdx.y * TBM;
    const int col_base = blockIdx.x * TBN;

    float acc[2][8][4];
#pragma unroll
    for (int i = 0; i < 2; i++)
#pragma unroll
        for (int j = 0; j < 8; j++)
#pragma unroll
            for (int k = 0; k < 4; k++) acc[i][j][k] = 0.0f;

    const uint32_t a_lane = (uint32_t)((warp_m * 32 + (lane & 15)) * AST +
                                       (lane >> 4) * 16);
    const uint32_t b_lane = (uint32_t)((((lane >> 3) & 1) * 8 + (lane & 7)) * BST +
                                       (warp_n * 64 + (lane >> 4) * 8) * 2);

    GEMM_MAINLOOP(Ah, Wh, N, K)

    const int g = lane >> 2;
    const int tg = lane & 3;
    float bv0[8], bv1[8];
#pragma unroll
    for (int nj = 0; nj < 8; nj++) {
        const int gcol = col_base + warp_n * 64 + nj * 8 + tg * 2;
        bv0[nj] = bias[gcol];
        bv1[nj] = bias[gcol + 1];
    }

#pragma unroll
    for (int mi = 0; mi < 2; mi++) {
        const int r0 = row_base + warp_m * 32 + mi * 16 + g;
        const int r1 = r0 + 8;
        float w0 = 0.0f, w1 = 0.0f;
        if (EPI == 2) { w0 = wmix[r0]; w1 = wmix[r1]; }
#pragma unroll
        for (int nj = 0; nj < 8; nj++) {
            const int gcol = col_base + warp_n * 64 + nj * 8 + tg * 2;
            float v00 = acc[mi][nj][0] + bv0[nj], v01 = acc[mi][nj][1] + bv1[nj];
            float v10 = acc[mi][nj][2] + bv0[nj], v11 = acc[mi][nj][3] + bv1[nj];
            if (EPI == 2) {
                float2 xo0 = *(const float2*)&xold[(size_t)r0 * N + gcol];
                float2 xo1 = *(const float2*)&xold[(size_t)r1 * N + gcol];
                v00 = w0 * v00 + (1.0f - w0) * xo0.x;
                v01 = w0 * v01 + (1.0f - w0) * xo0.y;
                v10 = w1 * v10 + (1.0f - w1) * xo1.x;
                v11 = w1 * v11 + (1.0f - w1) * xo1.y;
            }
            if (WF) {
                *(float2*)&Cf[(size_t)r0 * N + gcol] = make_float2(v00, v01);
                *(float2*)&Cf[(size_t)r1 * N + gcol] = make_float2(v10, v11);
            }
            if (WH) {
                *(__half2*)&Chh[(size_t)r0 * N + gcol] =
                    __halves2half2(__float2half_rn(v00), __float2half_rn(v01));
                *(__half2*)&Chh[(size_t)r1 * N + gcol] =
                    __halves2half2(__float2half_rn(v10), __float2half_rn(v11));
            }
        }
    }
}

// ---------------------------------------------------------------------------
// Router head GEMV + ACT state update (one warp per token)
// ---------------------------------------------------------------------------
__global__ void router_act_kernel(const float* __restrict__ rh,
                                  const float* __restrict__ Rw2i,
                                  const float* __restrict__ Rb2i)
{
    const int warp = threadIdx.x >> 5;
    const int lane = threadIdx.x & 31;
    const int t = blockIdx.x * 8 + warp;
    if (t >= M_) return;

    const float* r = rh + (size_t)t * HALF_;
    float s = 0.0f;
#pragma unroll
    for (int k = lane; k < HALF_; k += 32) s += r[k] * Rw2i[k];
#pragma unroll
    for (int o = 16; o > 0; o >>= 1) s += __shfl_xor_sync(0xffffffffu, s, o);

    if (lane == 0) {
        const float logit = s + Rb2i[0];
        const float p = 1.0f / (1.0f + expf(-logit));
        const float cum = g_cum[t];
        const float still = g_still[t];
        const float rem = fmaxf(1.0f - cum, 0.0f);
        const bool halt = (cum + p >= ACT_TAU);
        const float w = (halt ? rem : p) * still;
        g_w[t] = w;
        g_cum[t] = cum + w;
        g_wsum[t] += w;
        g_still[t] = halt ? 0.0f : still;
    }
}

__global__ void init_state_kernel()
{
    const int t = blockIdx.x * 256 + threadIdx.x;
    if (t < M_) {
        g_cum[t] = 0.0f;
        g_still[t] = 1.0f;
        g_wsum[t] = 1.0f;
    }
}

__global__ void budget_kernel(float* __restrict__ out)
{
    __shared__ float sh[256];
    float s = 0.0f;
    for (int t = threadIdx.x; t < M_; t += 256) s += g_wsum[t];
    sh[threadIdx.x] = s;
    __syncthreads();
#pragma unroll
    for (int o = 128; o > 0; o >>= 1) {
        if (threadIdx.x < o) sh[threadIdx.x] += sh[threadIdx.x + o];
        __syncthreads();
    }
    if (threadIdx.x == 0) {
        const float avg = sh[0] / (float)M_;
        const float d = avg - TARGET_DEPTH;
        const float rl = d > 0.0f ? d : 0.0f;
        out[0] = BUDGET_WEIGHT * rl * rl;
    }
}

// ---------------------------------------------------------------------------
// Launch
// ---------------------------------------------------------------------------
extern "C" void kernel_launch(void* const* d_in, const int* in_sizes, int n_in,
                              void* d_out, int out_size)
{
    const float* x_in = (const float*)d_in[0];
    const float* Wb1  = (const float*)d_in[1];
    const float* bb1  = (const float*)d_in[2];
    const float* Wb2  = (const float*)d_in[3];
    const float* bb2  = (const float*)d_in[4];
    const float* Rw1  = (const float*)d_in[5];  // (3, 1025, 512)
    const float* Rb1  = (const float*)d_in[6];  // (3, 512)
    const float* Rw2  = (const float*)d_in[7];  // (3, 512, 1)
    const float* Rb2  = (const float*)d_in[8];  // (3, 1)
    float* out = (float*)d_out;

    cudaFuncSetAttribute(g1_router,    cudaFuncAttributeMaxDynamicSharedMemorySize, SMEM_BYTES);
    cudaFuncSetAttribute(tgemm<0,1,1>, cudaFuncAttributeMaxDynamicSharedMemorySize, SMEM_BYTES);
    cudaFuncSetAttribute(tgemm<2,1,1>, cudaFuncAttributeMaxDynamicSharedMemorySize, SMEM_BYTES);
    cudaFuncSetAttribute(tgemm<2,1,0>, cudaFuncAttributeMaxDynamicSharedMemorySize, SMEM_BYTES);

    __half *W1h, *W2h, *R1h, *xh, *hh;
    float *gx, *grh, *gw;
    cudaGetSymbolAddress((void**)&W1h, g_W1h);
    cudaGetSymbolAddress((void**)&W2h, g_W2h);
    cudaGetSymbolAddress((void**)&R1h, g_R1h);
    cudaGetSymbolAddress((void**)&xh,  g_xh);
    cudaGetSymbolAddress((void**)&hh,  g_hh);
    cudaGetSymbolAddress((void**)&gx,  g_x);
    cudaGetSymbolAddress((void**)&grh, g_rh);
    cudaGetSymbolAddress((void**)&gw,  g_w);

    init_state_kernel<<<M_ / 256, 256>>>();

    // convert weights + input activations to fp16
    {
        int n4;
        n4 = H_ * DFF_ / 4;
        split_hi_kernel<<<(n4 + 255) / 256, 256>>>(Wb1, W1h, n4);
        split_hi_kernel<<<(n4 + 255) / 256, 256>>>(Wb2, W2h, n4);
        n4 = 3 * RW1_ROWS * HALF_ / 4;
        split_hi_kernel<<<(n4 + 255) / 256, 256>>>(Rw1, R1h, n4);
        n4 = M_ * H_ / 4;
        split_hi_kernel<<<(n4 + 255) / 256, 256>>>(x_in, xh, n4);
    }

    dim3 blk(256);
    dim3 gr1(32, M_ / TBM);            // body GEMM1 alone (first pass)
    dim3 gr1r(36, M_ / TBM);           // body GEMM1 + fused router tiles
    dim3 gr2(H_ / TBN, M_ / TBM);      // body GEMM2: 8 x 64

    // Mandatory first body pass: h = gelu(x W1 + b1); x = h W2 + b2
    g1_router<<<gr1, blk, SMEM_BYTES>>>(xh, W1h, bb1, hh, R1h, Rb1, grh);
    tgemm<0,1,1><<<gr2, blk, SMEM_BYTES>>>(hh, W2h, bb2, gx, xh,
                                           M_, H_, DFF_, nullptr, nullptr);

    for (int i = 0; i < 3; i++) {
        // Fused: h = gelu(x W1 + b1)  AND  rh = gelu(x Rw1_i + Rb1_i)
        const __half* R1hi = R1h + (size_t)i * RW1_ROWS * HALF_;
        g1_router<<<gr1r, blk, SMEM_BYTES>>>(xh, W1h, bb1, hh,
                                             R1hi, Rb1 + i * HALF_, grh);
        router_act_kernel<<<M_ / 8, 256>>>(grh, Rw2 + (size_t)i * HALF_, Rb2 + i);

        // Body GEMM2 + fused ACT soft mix
        if (i < 2) {
            tgemm<2,1,1><<<gr2, blk, SMEM_BYTES>>>(hh, W2h, bb2, gx, xh,
                                                   M_, H_, DFF_, gw, gx);
        } else {
            tgemm<2,1,0><<<gr2, blk, SMEM_BYTES>>>(hh, W2h, bb2, out, nullptr,
                                                   M_, H_, DFF_, gw, gx);
        }
    }

    if (out_size > (int)((size_t)M_ * H_))
        budget_kernel<<<1, 256>>>(out + (size_t)M_ * H_);
}

// round 15
// speedup vs baseline: 1.9282x; 1.1298x over previous
#include <cuda_runtime.h>
#include <cuda_fp16.h>
#include <math.h>
#include <stdint.h>

// ---------------------------------------------------------------------------
// Problem constants
// ---------------------------------------------------------------------------
#define B_ 4
#define T_ 2048
#define H_ 1024
#define DFF_ 4096
#define M_ (B_ * T_)      // 8192 tokens
#define HALF_ (H_ / 2)    // 512
#define ACT_TAU 0.99f
#define TARGET_DEPTH 2.5f
#define BUDGET_WEIGHT 0.01f
#define RW1_ROWS 1025

// ---------------------------------------------------------------------------
// Device scratch (no allocations allowed)
// ---------------------------------------------------------------------------
__device__ __align__(16) __half g_W1h[(size_t)H_ * DFF_];
__device__ __align__(16) __half g_W2h[(size_t)DFF_ * H_];
__device__ __align__(16) __half g_R1h[(size_t)3 * RW1_ROWS * HALF_];
__device__ __align__(16) __half g_xh[(size_t)M_ * H_];
__device__ __align__(16) __half g_hh[(size_t)M_ * DFF_];
__device__ float g_x[(size_t)M_ * H_];
__device__ float g_rh[(size_t)M_ * HALF_];
__device__ float g_w[M_];
__device__ float g_cum[M_];
__device__ float g_still[M_];
__device__ float g_wsum[M_];

// ---------------------------------------------------------------------------
// Helpers
// ---------------------------------------------------------------------------
__device__ __forceinline__ uint32_t smem_u32(const void* p) {
    uint32_t a;
    asm("{ .reg .u64 t; cvta.to.shared.u64 t, %1; cvt.u32.u64 %0, t; }"
        : "=r"(a) : "l"(p));
    return a;
}

__device__ __forceinline__ float gelu_exact(float v) {
    return 0.5f * v * (1.0f + erff(v * 0.70710678118654752440f));
}

__device__ __forceinline__ void cpa16(uint32_t dst, const void* src) {
    asm volatile("cp.async.cg.shared.global [%0], [%1], 16;" :: "r"(dst), "l"(src));
}
__device__ __forceinline__ void cpa_commit() {
    asm volatile("cp.async.commit_group;" ::: "memory");
}
template <int N>
__device__ __forceinline__ void cpa_wait() {
    asm volatile("cp.async.wait_group %0;" :: "n"(N) : "memory");
}

__device__ __forceinline__ void ldsm_x4(uint32_t* r, uint32_t addr) {
    asm volatile("ldmatrix.sync.aligned.m8n8.x4.shared.b16 {%0,%1,%2,%3}, [%4];"
                 : "=r"(r[0]), "=r"(r[1]), "=r"(r[2]), "=r"(r[3]) : "r"(addr));
}
__device__ __forceinline__ void ldsm_x4t(uint32_t* r, uint32_t addr) {
    asm volatile("ldmatrix.sync.aligned.m8n8.x4.trans.shared.b16 {%0,%1,%2,%3}, [%4];"
                 : "=r"(r[0]), "=r"(r[1]), "=r"(r[2]), "=r"(r[3]) : "r"(addr));
}

// mma m16n8k16 fp16 -> fp32 accum
__device__ __forceinline__ void mma_f16(float* c, const uint32_t* a,
                                        uint32_t b0, uint32_t b1) {
    asm volatile(
        "mma.sync.aligned.m16n8k16.row.col.f32.f16.f16.f32 "
        "{%0,%1,%2,%3}, {%4,%5,%6,%7}, {%8,%9}, {%0,%1,%2,%3};"
        : "+f"(c[0]), "+f"(c[1]), "+f"(c[2]), "+f"(c[3])
        : "r"(a[0]), "r"(a[1]), "r"(a[2]), "r"(a[3]), "r"(b0), "r"(b1));
}

// ---------------------------------------------------------------------------
// fp32 -> fp16 convert
// ---------------------------------------------------------------------------
__global__ void split_hi_kernel(const float* __restrict__ src,
                                __half* __restrict__ hi, int n4)
{
    int i = blockIdx.x * 256 + threadIdx.x;
    if (i >= n4) return;
    float4 v = ((const float4*)src)[i];
    ((__half2*)hi)[i * 2 + 0] = __halves2half2(__float2half_rn(v.x), __float2half_rn(v.y));
    ((__half2*)hi)[i * 2 + 1] = __halves2half2(__float2half_rn(v.z), __float2half_rn(v.w));
}

// ---------------------------------------------------------------------------
// Tile config: CTA 64x128, 128 threads (4 warps, 2x2 of 32x64 warp tiles),
// K-chunk 32, 2-stage cp.async, 5 CTAs/SM (20 warps/SM).
// ---------------------------------------------------------------------------
#define TBM 64
#define TBN 128
#define TBK 32
#define NTHR 128
#define AST 80       // A smem row stride bytes (32 fp16 = 64B + 16 pad)
#define BST 272      // B smem row stride bytes (128 fp16 = 256B + 16 pad)
#define A_BYTES (TBM * AST)                 // 5120
#define B_BYTES (32 * BST)                  // 8704
#define ST_AH 0
#define ST_BH A_BYTES
#define STAGE_BYTES (A_BYTES + B_BYTES)     // 13824
#define SMEM_BYTES (2 * STAGE_BYTES)        // 27648

// Mainloop: acc[2][8][4] = A_h[M,K] * W_h[K,N], per-output math identical to
// the 128x128 version (same TBK, same k16 order) -> bit-identical results.
#define GEMM_MAINLOOP(Ah_, Wh_, ldw_, K_)                                        \
    const int NC = (K_) / TBK;                                                   \
    auto load_chunk = [&](int c) {                                               \
        const uint32_t st = sm + (uint32_t)((c & 1) * STAGE_BYTES);              \
        const int k0 = c * TBK;                                                  \
        _Pragma("unroll")                                                        \
        for (int s = 0; s < 2; s++) {                                            \
            int gidx = tid + NTHR * s;       /* 0..255 A granules */             \
            int r = gidx >> 2, o = gidx & 3;                                     \
            size_t go = (size_t)(row_base + r) * (K_) + k0 + o * 8;              \
            cpa16(st + ST_AH + (uint32_t)(r * AST + o * 16), (Ah_) + go);        \
        }                                                                        \
        _Pragma("unroll")                                                        \
        for (int s = 0; s < 4; s++) {                                            \
            int gidx = tid + NTHR * s;       /* 0..511 B granules */             \
            int r = gidx >> 4, o = gidx & 15;                                    \
            size_t go = (size_t)(k0 + r) * (ldw_) + col_base + o * 8;            \
            cpa16(st + ST_BH + (uint32_t)(r * BST + o * 16), (Wh_) + go);        \
        }                                                                        \
        cpa_commit();                                                            \
    };                                                                           \
    load_chunk(0);                                                               \
    for (int c = 0; c < NC; c++) {                                               \
        if (c + 1 < NC) { load_chunk(c + 1); cpa_wait<1>(); }                    \
        else            { cpa_wait<0>(); }                                       \
        __syncthreads();                                                         \
        const uint32_t st = sm + (uint32_t)((c & 1) * STAGE_BYTES);              \
        _Pragma("unroll")                                                        \
        for (int ks = 0; ks < 2; ks++) {                                         \
            uint32_t ah[2][4], bh[4][4];                                         \
            _Pragma("unroll")                                                    \
            for (int mi = 0; mi < 2; mi++)                                       \
                ldsm_x4(ah[mi], st + ST_AH + a_lane +                            \
                                (uint32_t)(mi * 16 * AST + ks * 32));            \
            _Pragma("unroll")                                                    \
            for (int ni = 0; ni < 4; ni++)                                       \
                ldsm_x4t(bh[ni], st + ST_BH + b_lane +                           \
                                 (uint32_t)(ks * 16 * BST + ni * 32));           \
            _Pragma("unroll")                                                    \
            for (int ni = 0; ni < 4; ni++)                                       \
                _Pragma("unroll")                                                \
                for (int mi = 0; mi < 2; mi++) {                                 \
                    mma_f16(acc[mi][ni * 2 + 0], ah[mi], bh[ni][0], bh[ni][1]);  \
                    mma_f16(acc[mi][ni * 2 + 1], ah[mi], bh[ni][2], bh[ni][3]);  \
                }                                                                \
        }                                                                        \
        __syncthreads();                                                         \
    }

// ---------------------------------------------------------------------------
// Fused body-GEMM1 + router-GEMM kernel.
//   bx < 32 : h-tile  = gelu(x*W1 + bb1)      -> hh (fp16, ld 4096)
//   bx >= 32: rh-tile = gelu(x*Rw1_i + Rb1_i) -> rh (fp32, ld 512)
// ---------------------------------------------------------------------------
__global__ __launch_bounds__(NTHR, 5)
void g1_router(const __half* __restrict__ Ah,
               const __half* __restrict__ W1, const float* __restrict__ b1,
               __half* __restrict__ Chh,
               const __half* __restrict__ Wr, const float* __restrict__ br,
               float* __restrict__ Crh)
{
    extern __shared__ char smp[];
    const uint32_t sm = smem_u32(smp);

    const int tid = threadIdx.x;
    const int lane = tid & 31;
    const int warp = tid >> 5;
    const int warp_m = warp & 1;          // 2 warps along M -> 32 rows each
    const int warp_n = warp >> 1;         // 2 warps along N -> 64 cols each
    const int row_base = blockIdx.y * TBM;

    const bool is_r = (blockIdx.x >= 32);
    const int col_base = (is_r ? (blockIdx.x - 32) : blockIdx.x) * TBN;
    const __half* Wh = is_r ? Wr : W1;
    const float* bias = is_r ? br : b1;
    const int ldw = is_r ? HALF_ : DFF_;

    float acc[2][8][4];
#pragma unroll
    for (int i = 0; i < 2; i++)
#pragma unroll
        for (int j = 0; j < 8; j++)
#pragma unroll
            for (int k = 0; k < 4; k++) acc[i][j][k] = 0.0f;

    const uint32_t a_lane = (uint32_t)((warp_m * 32 + (lane & 15)) * AST +
                                       (lane >> 4) * 16);
    const uint32_t b_lane = (uint32_t)((((lane >> 3) & 1) * 8 + (lane & 7)) * BST +
                                       (warp_n * 64 + (lane >> 4) * 8) * 2);

    GEMM_MAINLOOP(Ah, Wh, ldw, H_)

    const int g = lane >> 2;
    const int tg = lane & 3;
    float bv0[8], bv1[8];
#pragma unroll
    for (int nj = 0; nj < 8; nj++) {
        const int gcol = col_base + warp_n * 64 + nj * 8 + tg * 2;
        bv0[nj] = bias[gcol];
        bv1[nj] = bias[gcol + 1];
    }

#pragma unroll
    for (int mi = 0; mi < 2; mi++) {
        const int r0 = row_base + warp_m * 32 + mi * 16 + g;
        const int r1 = r0 + 8;
#pragma unroll
        for (int nj = 0; nj < 8; nj++) {
            const int gcol = col_base + warp_n * 64 + nj * 8 + tg * 2;
            float v00 = gelu_exact(acc[mi][nj][0] + bv0[nj]);
            float v01 = gelu_exact(acc[mi][nj][1] + bv1[nj]);
            float v10 = gelu_exact(acc[mi][nj][2] + bv0[nj]);
            float v11 = gelu_exact(acc[mi][nj][3] + bv1[nj]);
            if (is_r) {
                *(float2*)&Crh[(size_t)r0 * HALF_ + gcol] = make_float2(v00, v01);
                *(float2*)&Crh[(size_t)r1 * HALF_ + gcol] = make_float2(v10, v11);
            } else {
                *(__half2*)&Chh[(size_t)r0 * DFF_ + gcol] =
                    __halves2half2(__float2half_rn(v00), __float2half_rn(v01));
                *(__half2*)&Chh[(size_t)r1 * DFF_ + gcol] =
                    __halves2half2(__float2half_rn(v10), __float2half_rn(v11));
            }
        }
    }
}

// ---------------------------------------------------------------------------
// Generic GEMM (used for body GEMM2).
// EPI: 0=bias, 2=bias+ACT mix.  WF: write fp32 Cf.  WH: write fp16 Chh.
// ---------------------------------------------------------------------------
template <int EPI, int WF, int WH>
__global__ __launch_bounds__(NTHR, 5)
void tgemm(const __half* __restrict__ Ah, const __half* __restrict__ Wh,
           const float* __restrict__ bias, float* __restrict__ Cf,
           __half* __restrict__ Chh,
           int M, int N, int K,
           const float* __restrict__ wmix, const float* __restrict__ xold)
{
    extern __shared__ char smp[];
    const uint32_t sm = smem_u32(smp);

    const int tid = threadIdx.x;
    const int lane = tid & 31;
    const int warp = tid >> 5;
    const int warp_m = warp & 1;
    const int warp_n = warp >> 1;
    const int row_base = blockIdx.y * TBM;
    const int col_base = blockIdx.x * TBN;

    float acc[2][8][4];
#pragma unroll
    for (int i = 0; i < 2; i++)
#pragma unroll
        for (int j = 0; j < 8; j++)
#pragma unroll
            for (int k = 0; k < 4; k++) acc[i][j][k] = 0.0f;

    const uint32_t a_lane = (uint32_t)((warp_m * 32 + (lane & 15)) * AST +
                                       (lane >> 4) * 16);
    const uint32_t b_lane = (uint32_t)((((lane >> 3) & 1) * 8 + (lane & 7)) * BST +
                                       (warp_n * 64 + (lane >> 4) * 8) * 2);

    GEMM_MAINLOOP(Ah, Wh, N, K)

    const int g = lane >> 2;
    const int tg = lane & 3;
    float bv0[8], bv1[8];
#pragma unroll
    for (int nj = 0; nj < 8; nj++) {
        const int gcol = col_base + warp_n * 64 + nj * 8 + tg * 2;
        bv0[nj] = bias[gcol];
        bv1[nj] = bias[gcol + 1];
    }

#pragma unroll
    for (int mi = 0; mi < 2; mi++) {
        const int r0 = row_base + warp_m * 32 + mi * 16 + g;
        const int r1 = r0 + 8;
        float w0 = 0.0f, w1 = 0.0f;
        if (EPI == 2) { w0 = wmix[r0]; w1 = wmix[r1]; }
#pragma unroll
        for (int nj = 0; nj < 8; nj++) {
            const int gcol = col_base + warp_n * 64 + nj * 8 + tg * 2;
            float v00 = acc[mi][nj][0] + bv0[nj], v01 = acc[mi][nj][1] + bv1[nj];
            float v10 = acc[mi][nj][2] + bv0[nj], v11 = acc[mi][nj][3] + bv1[nj];
            if (EPI == 2) {
                float2 xo0 = *(const float2*)&xold[(size_t)r0 * N + gcol];
                float2 xo1 = *(const float2*)&xold[(size_t)r1 * N + gcol];
                v00 = w0 * v00 + (1.0f - w0) * xo0.x;
                v01 = w0 * v01 + (1.0f - w0) * xo0.y;
                v10 = w1 * v10 + (1.0f - w1) * xo1.x;
                v11 = w1 * v11 + (1.0f - w1) * xo1.y;
            }
            if (WF) {
                *(float2*)&Cf[(size_t)r0 * N + gcol] = make_float2(v00, v01);
                *(float2*)&Cf[(size_t)r1 * N + gcol] = make_float2(v10, v11);
            }
            if (WH) {
                *(__half2*)&Chh[(size_t)r0 * N + gcol] =
                    __halves2half2(__float2half_rn(v00), __float2half_rn(v01));
                *(__half2*)&Chh[(size_t)r1 * N + gcol] =
                    __halves2half2(__float2half_rn(v10), __float2half_rn(v11));
            }
        }
    }
}

// ---------------------------------------------------------------------------
// Router head GEMV + ACT state update (one warp per token)
// ---------------------------------------------------------------------------
__global__ void router_act_kernel(const float* __restrict__ rh,
                                  const float* __restrict__ Rw2i,
                                  const float* __restrict__ Rb2i)
{
    const int warp = threadIdx.x >> 5;
    const int lane = threadIdx.x & 31;
    const int t = blockIdx.x * 8 + warp;
    if (t >= M_) return;

    const float* r = rh + (size_t)t * HALF_;
    float s = 0.0f;
#pragma unroll
    for (int k = lane; k < HALF_; k += 32) s += r[k] * Rw2i[k];
#pragma unroll
    for (int o = 16; o > 0; o >>= 1) s += __shfl_xor_sync(0xffffffffu, s, o);

    if (lane == 0) {
        const float logit = s + Rb2i[0];
        const float p = 1.0f / (1.0f + expf(-logit));
        const float cum = g_cum[t];
        const float still = g_still[t];
        const float rem = fmaxf(1.0f - cum, 0.0f);
        const bool halt = (cum + p >= ACT_TAU);
        const float w = (halt ? rem : p) * still;
        g_w[t] = w;
        g_cum[t] = cum + w;
        g_wsum[t] += w;
        g_still[t] = halt ? 0.0f : still;
    }
}

__global__ void init_state_kernel()
{
    const int t = blockIdx.x * 256 + threadIdx.x;
    if (t < M_) {
        g_cum[t] = 0.0f;
        g_still[t] = 1.0f;
        g_wsum[t] = 1.0f;
    }
}

__global__ void budget_kernel(float* __restrict__ out)
{
    __shared__ float sh[256];
    float s = 0.0f;
    for (int t = threadIdx.x; t < M_; t += 256) s += g_wsum[t];
    sh[threadIdx.x] = s;
    __syncthreads();
#pragma unroll
    for (int o = 128; o > 0; o >>= 1) {
        if (threadIdx.x < o) sh[threadIdx.x] += sh[threadIdx.x + o];
        __syncthreads();
    }
    if (threadIdx.x == 0) {
        const float avg = sh[0] / (float)M_;
        const float d = avg - TARGET_DEPTH;
        const float rl = d > 0.0f ? d : 0.0f;
        out[0] = BUDGET_WEIGHT * rl * rl;
    }
}

// ---------------------------------------------------------------------------
// Launch
// ---------------------------------------------------------------------------
extern "C" void kernel_launch(void* const* d_in, const int* in_sizes, int n_in,
                              void* d_out, int out_size)
{
    const float* x_in = (const float*)d_in[0];
    const float* Wb1  = (const float*)d_in[1];
    const float* bb1  = (const float*)d_in[2];
    const float* Wb2  = (const float*)d_in[3];
    const float* bb2  = (const float*)d_in[4];
    const float* Rw1  = (const float*)d_in[5];  // (3, 1025, 512)
    const float* Rb1  = (const float*)d_in[6];  // (3, 512)
    const float* Rw2  = (const float*)d_in[7];  // (3, 512, 1)
    const float* Rb2  = (const float*)d_in[8];  // (3, 1)
    float* out = (float*)d_out;

    cudaFuncSetAttribute(g1_router,    cudaFuncAttributeMaxDynamicSharedMemorySize, SMEM_BYTES);
    cudaFuncSetAttribute(tgemm<0,1,1>, cudaFuncAttributeMaxDynamicSharedMemorySize, SMEM_BYTES);
    cudaFuncSetAttribute(tgemm<2,1,1>, cudaFuncAttributeMaxDynamicSharedMemorySize, SMEM_BYTES);
    cudaFuncSetAttribute(tgemm<2,1,0>, cudaFuncAttributeMaxDynamicSharedMemorySize, SMEM_BYTES);

    __half *W1h, *W2h, *R1h, *xh, *hh;
    float *gx, *grh, *gw;
    cudaGetSymbolAddress((void**)&W1h, g_W1h);
    cudaGetSymbolAddress((void**)&W2h, g_W2h);
    cudaGetSymbolAddress((void**)&R1h, g_R1h);
    cudaGetSymbolAddress((void**)&xh,  g_xh);
    cudaGetSymbolAddress((void**)&hh,  g_hh);
    cudaGetSymbolAddress((void**)&gx,  g_x);
    cudaGetSymbolAddress((void**)&grh, g_rh);
    cudaGetSymbolAddress((void**)&gw,  g_w);

    init_state_kernel<<<M_ / 256, 256>>>();

    // convert weights + input activations to fp16
    {
        int n4;
        n4 = H_ * DFF_ / 4;
        split_hi_kernel<<<(n4 + 255) / 256, 256>>>(Wb1, W1h, n4);
        split_hi_kernel<<<(n4 + 255) / 256, 256>>>(Wb2, W2h, n4);
        n4 = 3 * RW1_ROWS * HALF_ / 4;
        split_hi_kernel<<<(n4 + 255) / 256, 256>>>(Rw1, R1h, n4);
        n4 = M_ * H_ / 4;
        split_hi_kernel<<<(n4 + 255) / 256, 256>>>(x_in, xh, n4);
    }

    dim3 blk(NTHR);
    dim3 gr1(32, M_ / TBM);            // body GEMM1 alone (first pass)
    dim3 gr1r(36, M_ / TBM);           // body GEMM1 + fused router tiles
    dim3 gr2(H_ / TBN, M_ / TBM);      // body GEMM2: 8 x 128

    // Mandatory first body pass: h = gelu(x W1 + b1); x = h W2 + b2
    g1_router<<<gr1, blk, SMEM_BYTES>>>(xh, W1h, bb1, hh, R1h, Rb1, grh);
    tgemm<0,1,1><<<gr2, blk, SMEM_BYTES>>>(hh, W2h, bb2, gx, xh,
                                           M_, H_, DFF_, nullptr, nullptr);

    for (int i = 0; i < 3; i++) {
        // Fused: h = gelu(x W1 + b1)  AND  rh = gelu(x Rw1_i + Rb1_i)
        const __half* R1hi = R1h + (size_t)i * RW1_ROWS * HALF_;
        g1_router<<<gr1r, blk, SMEM_BYTES>>>(xh, W1h, bb1, hh,
                                             R1hi, Rb1 + i * HALF_, grh);
        router_act_kernel<<<M_ / 8, 256>>>(grh, Rw2 + (size_t)i * HALF_, Rb2 + i);

        // Body GEMM2 + fused ACT soft mix
        if (i < 2) {
            tgemm<2,1,1><<<gr2, blk, SMEM_BYTES>>>(hh, W2h, bb2, gx, xh,
                                                   M_, H_, DFF_, gw, gx);
        } else {
            tgemm<2,1,0><<<gr2, blk, SMEM_BYTES>>>(hh, W2h, bb2, out, nullptr,
                                                   M_, H_, DFF_, gw, gx);
        }
    }

    if (out_size > (int)((size_t)M_ * H_))
        budget_kernel<<<1, 256>>>(out + (size_t)M_ * H_);
}